// round 12
// baseline (speedup 1.0000x reference)
#include <cuda_runtime.h>
#include <cuda_bf16.h>
#include <cstdint>

#define T_SEQ 2048
#define BATCH 32
#define DIM   512
#define HID   512
#define G4    2048
#define NJ    (T_SEQ * BATCH)   // 65536
#define NCTA  128               // recurrent CTAs: 4 units each

// ---------------- static device scratch ----------------
__device__ float    g_xproj[(size_t)G4 * NJ];                  // [g][t*32+b] fp32 (512MB)
__device__ unsigned g_xhi[(size_t)BATCH * T_SEQ * DIM / 2];    // bf16 pairs along d
__device__ unsigned g_xlo[(size_t)BATCH * T_SEQ * DIM / 2];
__device__ unsigned g_whi[(size_t)G4 * DIM / 2];
__device__ unsigned g_wlo[(size_t)G4 * DIM / 2];
__device__ unsigned g_hhi[2][(HID / 2) * BATCH];               // word idx = k2*32+b
__device__ unsigned g_hlo[2][(HID / 2) * BATCH];
__device__ unsigned g_arr[8 * 32];   // sharded arrival counters (128B apart)
__device__ unsigned g_go;            // broadcast epoch flag

// ---------------- helpers ----------------
__device__ __forceinline__ void mma_bf16(float c[4], const unsigned a[4],
                                         unsigned b0, unsigned b1) {
    asm volatile(
        "mma.sync.aligned.m16n8k16.row.col.f32.bf16.bf16.f32 "
        "{%0,%1,%2,%3}, {%4,%5,%6,%7}, {%8,%9}, {%0,%1,%2,%3};\n"
        : "+f"(c[0]), "+f"(c[1]), "+f"(c[2]), "+f"(c[3])
        : "r"(a[0]), "r"(a[1]), "r"(a[2]), "r"(a[3]), "r"(b0), "r"(b1));
}

__device__ __forceinline__ unsigned split_pack(float v0, float v1, unsigned& lo_bits) {
    __nv_bfloat162 hi = __floats2bfloat162_rn(v0, v1);
    __nv_bfloat162 lo = __floats2bfloat162_rn(v0 - __bfloat162float(hi.x),
                                              v1 - __bfloat162float(hi.y));
    lo_bits = *reinterpret_cast<unsigned*>(&lo);
    return *reinterpret_cast<unsigned*>(&hi);
}

__device__ __forceinline__ float sigf(float x) {
    return __fdividef(1.f, 1.f + __expf(-x));
}
__device__ __forceinline__ float tanh_fast(float x) {
    return __fdividef(2.f, 1.f + __expf(-2.f * x)) - 1.f;
}

__device__ __forceinline__ void red_release(unsigned* p) {
    asm volatile("red.release.gpu.global.add.u32 [%0], %1;" :: "l"(p), "r"(1u) : "memory");
}
__device__ __forceinline__ unsigned ld_acquire(const unsigned* p) {
    unsigned v;
    asm volatile("ld.acquire.gpu.global.u32 %0, [%1];" : "=r"(v) : "l"(p) : "memory");
    return v;
}
__device__ __forceinline__ void st_release(unsigned* p, unsigned v) {
    asm volatile("st.release.gpu.global.u32 [%0], %1;" :: "l"(p), "r"(v) : "memory");
}

// =====================================================================
// convert: split input & W_ih into bf16 hi/lo packed-pair planes
// =====================================================================
__global__ void convert_kernel(const float* __restrict__ x,
                               const float* __restrict__ wih)
{
    const size_t n_x = (size_t)BATCH * T_SEQ * DIM / 2;
    const size_t n_w = (size_t)G4 * DIM / 2;
    const size_t stride = (size_t)gridDim.x * blockDim.x;
    for (size_t i = blockIdx.x * (size_t)blockDim.x + threadIdx.x;
         i < n_x; i += stride) {
        float2 v = reinterpret_cast<const float2*>(x)[i];
        unsigned lo;
        unsigned hi = split_pack(v.x, v.y, lo);
        g_xhi[i] = hi; g_xlo[i] = lo;
    }
    for (size_t i = blockIdx.x * (size_t)blockDim.x + threadIdx.x;
         i < n_w; i += stride) {
        float2 v = reinterpret_cast<const float2*>(wih)[i];
        unsigned lo;
        unsigned hi = split_pack(v.x, v.y, lo);
        g_whi[i] = hi; g_wlo[i] = lo;
    }
}

// =====================================================================
// init: h planes (buffer 0) from h0, reset barrier state
// =====================================================================
__global__ void init_kernel(const float* __restrict__ h0)
{
    int i = blockIdx.x * blockDim.x + threadIdx.x;
    if (i < (HID / 2) * BATCH) {
        int k2 = i >> 5, b = i & 31;
        float v0 = h0[b * HID + 2 * k2];
        float v1 = h0[b * HID + 2 * k2 + 1];
        unsigned lo;
        unsigned hi = split_pack(v0, v1, lo);
        g_hhi[0][i] = hi; g_hlo[0][i] = lo;
    }
    if (i < 8 * 32) g_arr[i] = 0u;
    if (i == 256) g_go = 0u;
}

// =====================================================================
// Phase 1: x_proj via bf16x3 mma, 2-stage pipelined (unchanged from R6)
// =====================================================================
#define SA 20
#define XPLANE (128 * SA)
#define XBUF   (4 * XPLANE)
#define XSMEM_WORDS (2 * XBUF)
#define XSMEM_BYTES (XSMEM_WORDS * 4)

__global__ __launch_bounds__(256) void xproj_kernel(
    const float* __restrict__ b_ih,
    const float* __restrict__ b_hh)
{
    extern __shared__ unsigned xsm[];

    const int tid = threadIdx.x;
    const int w = tid >> 5, lane = tid & 31;
    const int gq = lane >> 2, tg = lane & 3;
    const int gm0 = blockIdx.x * 128;
    const int jn0 = blockIdx.y * 128;
    const int wm = (w >> 2) * 64;
    const int wn = (w & 3) * 32;

    int s_m[2], s_q4[2];
    size_t gwA[2], gwB[2];
    #pragma unroll
    for (int i = 0; i < 2; ++i) {
        int idx = tid + i * 256;
        int m = idx >> 2, q4 = (idx & 3) * 4;
        s_m[i] = m; s_q4[i] = q4;
        gwA[i] = (size_t)(gm0 + m) * (DIM / 2) + q4;
        int b = m & 31;
        int t = (jn0 + m) >> 5;
        gwB[i] = ((size_t)b * T_SEQ + t) * (DIM / 2) + q4;
    }

    float acc[4][4][4];
    #pragma unroll
    for (int m = 0; m < 4; ++m)
        #pragma unroll
        for (int n = 0; n < 4; ++n)
            #pragma unroll
            for (int r = 0; r < 4; ++r) acc[m][n][r] = 0.f;

    uint4 rAh[2], rAl[2], rBh[2], rBl[2];

    #pragma unroll
    for (int i = 0; i < 2; ++i) {
        rAh[i] = *reinterpret_cast<const uint4*>(&g_whi[gwA[i]]);
        rAl[i] = *reinterpret_cast<const uint4*>(&g_wlo[gwA[i]]);
        rBh[i] = *reinterpret_cast<const uint4*>(&g_xhi[gwB[i]]);
        rBl[i] = *reinterpret_cast<const uint4*>(&g_xlo[gwB[i]]);
    }
    {
        unsigned* buf = xsm;
        #pragma unroll
        for (int i = 0; i < 2; ++i) {
            int off = s_m[i] * SA + s_q4[i];
            *reinterpret_cast<uint4*>(&buf[off])              = rAh[i];
            *reinterpret_cast<uint4*>(&buf[XPLANE + off])     = rAl[i];
            *reinterpret_cast<uint4*>(&buf[2 * XPLANE + off]) = rBh[i];
            *reinterpret_cast<uint4*>(&buf[3 * XPLANE + off]) = rBl[i];
        }
    }
    __syncthreads();

    int p = 0;
    for (int c = 0; c < 16; ++c) {
        if (c + 1 < 16) {
            const size_t ko = (size_t)(c + 1) * 16;
            #pragma unroll
            for (int i = 0; i < 2; ++i) {
                rAh[i] = *reinterpret_cast<const uint4*>(&g_whi[gwA[i] + ko]);
                rAl[i] = *reinterpret_cast<const uint4*>(&g_wlo[gwA[i] + ko]);
                rBh[i] = *reinterpret_cast<const uint4*>(&g_xhi[gwB[i] + ko]);
                rBl[i] = *reinterpret_cast<const uint4*>(&g_xlo[gwB[i] + ko]);
            }
        }

        unsigned* Ahs = xsm + p * XBUF;
        unsigned* Als = Ahs + XPLANE;
        unsigned* Bhs = Ahs + 2 * XPLANE;
        unsigned* Bls = Ahs + 3 * XPLANE;

        #pragma unroll
        for (int kt = 0; kt < 2; ++kt) {
            const int k2o = kt * 8;
            unsigned bh[4][2], bl[4][2];
            #pragma unroll
            for (int n = 0; n < 4; ++n) {
                int j = wn + n * 8 + gq;
                bh[n][0] = Bhs[j * SA + k2o + tg];
                bh[n][1] = Bhs[j * SA + k2o + tg + 4];
                bl[n][0] = Bls[j * SA + k2o + tg];
                bl[n][1] = Bls[j * SA + k2o + tg + 4];
            }
            #pragma unroll
            for (int m = 0; m < 4; ++m) {
                int r0 = wm + m * 16 + gq;
                unsigned ah[4], al[4];
                ah[0] = Ahs[r0 * SA + k2o + tg];
                ah[1] = Ahs[(r0 + 8) * SA + k2o + tg];
                ah[2] = Ahs[r0 * SA + k2o + tg + 4];
                ah[3] = Ahs[(r0 + 8) * SA + k2o + tg + 4];
                al[0] = Als[r0 * SA + k2o + tg];
                al[1] = Als[(r0 + 8) * SA + k2o + tg];
                al[2] = Als[r0 * SA + k2o + tg + 4];
                al[3] = Als[(r0 + 8) * SA + k2o + tg + 4];
                #pragma unroll
                for (int n = 0; n < 4; ++n) {
                    mma_bf16(acc[m][n], ah, bh[n][0], bh[n][1]);
                    mma_bf16(acc[m][n], ah, bl[n][0], bl[n][1]);
                    mma_bf16(acc[m][n], al, bh[n][0], bh[n][1]);
                }
            }
        }

        if (c + 1 < 16) {
            unsigned* buf = xsm + (p ^ 1) * XBUF;
            #pragma unroll
            for (int i = 0; i < 2; ++i) {
                int off = s_m[i] * SA + s_q4[i];
                *reinterpret_cast<uint4*>(&buf[off])              = rAh[i];
                *reinterpret_cast<uint4*>(&buf[XPLANE + off])     = rAl[i];
                *reinterpret_cast<uint4*>(&buf[2 * XPLANE + off]) = rBh[i];
                *reinterpret_cast<uint4*>(&buf[3 * XPLANE + off]) = rBl[i];
            }
            __syncthreads();
            p ^= 1;
        }
    }

    #pragma unroll
    for (int m = 0; m < 4; ++m) {
        int g0 = gm0 + wm + m * 16 + gq;
        float bi0 = __ldg(b_ih + g0) + __ldg(b_hh + g0);
        float bi1 = __ldg(b_ih + g0 + 8) + __ldg(b_hh + g0 + 8);
        #pragma unroll
        for (int n = 0; n < 4; ++n) {
            int j0 = jn0 + wn + n * 8 + tg * 2;
            float2 v0 = make_float2(acc[m][n][0] + bi0, acc[m][n][1] + bi0);
            float2 v1 = make_float2(acc[m][n][2] + bi1, acc[m][n][3] + bi1);
            *reinterpret_cast<float2*>(g_xproj + (size_t)g0 * NJ + j0) = v0;
            *reinterpret_cast<float2*>(g_xproj + (size_t)(g0 + 8) * NJ + j0) = v1;
        }
    }
}

// =====================================================================
// Phase 2: persistent recurrent kernel (R6 design) with sharded-arrival
// sense-broadcast barrier.
// =====================================================================
#define HSW 40
#define SMEM_WORDS (2 * 256 * HSW + 8 * 16 * 33)
#define SMEM_BYTES (SMEM_WORDS * 4)

__global__ __launch_bounds__(256) void lstm_kernel(
    const float* __restrict__ W_hh,
    const float* __restrict__ c0,
    float* __restrict__ out)
{
    extern __shared__ unsigned smw[];
    unsigned* s_hhi = smw;                    // [256 k2][HSW]
    unsigned* s_hlo = smw + 256 * HSW;
    float*    part  = reinterpret_cast<float*>(smw + 2 * 256 * HSW); // [8][16][33]

    const int tid = threadIdx.x;
    const int cta = blockIdx.x;
    const int w = tid >> 5, lane = tid & 31;
    const int gq = lane >> 2, tg = lane & 3;

    // ---- W_hh frags into registers (hi/lo), once ----
    unsigned Ahi[4][4], Alo[4][4];
    #pragma unroll
    for (int kt = 0; kt < 4; ++kt) {
        #pragma unroll
        for (int i = 0; i < 4; ++i) {
            int r   = gq + ((i & 1) << 3);
            int k2l = tg + ((i >> 1) << 2);
            int kg  = w * 64 + kt * 16 + k2l * 2;
            int G   = (r & 3) * HID + cta * 4 + (r >> 2);
            float w0 = __ldg(W_hh + (size_t)G * HID + kg);
            float w1 = __ldg(W_hh + (size_t)G * HID + kg + 1);
            unsigned lo;
            Ahi[kt][i] = split_pack(w0, w1, lo);
            Alo[kt][i] = lo;
        }
    }

    // cell threads: tid<64, pair pr = tid>>5 (units 2pr,2pr+1), batch b
    const int pr = tid >> 5;
    const int b  = lane;
    float cst[2] = {0.f, 0.f};
    if (tid < 64) {
        cst[0] = __ldg(c0 + b * HID + cta * 4 + 2 * pr);
        cst[1] = __ldg(c0 + b * HID + cta * 4 + 2 * pr + 1);
    }

    for (int t = 0; t < T_SEQ; ++t) {
        const int cur = t & 1;

        // ---- xp(t) loads fired early; consumed after sync1 ----
        float xp[8];
        if (tid < 64) {
            #pragma unroll
            for (int j2 = 0; j2 < 2; ++j2)
                #pragma unroll
                for (int q = 0; q < 4; ++q) {
                    int G = q * HID + cta * 4 + 2 * pr + j2;
                    xp[j2 * 4 + q] =
                        __ldg(&g_xproj[(size_t)G * NJ + (size_t)t * 32 + b]);
                }
        }

        // ---- per-warp self-staging: warp w stages its own 32 k2 rows ----
        #pragma unroll
        for (int i = 0; i < 8; ++i) {
            int lin = w * 256 + i * 32 + lane;     // uint4 idx within plane
            int k2 = lin >> 3, b4 = (lin & 7) * 4;
            uint4 vh = __ldcg(reinterpret_cast<const uint4*>(&g_hhi[cur][lin * 4]));
            uint4 vl = __ldcg(reinterpret_cast<const uint4*>(&g_hlo[cur][lin * 4]));
            *reinterpret_cast<uint4*>(&s_hhi[k2 * HSW + b4]) = vh;
            *reinterpret_cast<uint4*>(&s_hlo[k2 * HSW + b4]) = vl;
        }
        // no syncthreads: warp consumes only its own staged slice

        // ---- mma: warp w covers k2 in [w*32, w*32+32) ----
        float acc[4][4];
        #pragma unroll
        for (int n = 0; n < 4; ++n)
            #pragma unroll
            for (int r = 0; r < 4; ++r) acc[n][r] = 0.f;

        #pragma unroll
        for (int kt = 0; kt < 4; ++kt) {
            const int base = w * 32 + kt * 8;
            #pragma unroll
            for (int n = 0; n < 4; ++n) {
                int col = n * 8 + gq;
                unsigned bh0 = s_hhi[(base + tg) * HSW + col];
                unsigned bh1 = s_hhi[(base + tg + 4) * HSW + col];
                unsigned bl0 = s_hlo[(base + tg) * HSW + col];
                unsigned bl1 = s_hlo[(base + tg + 4) * HSW + col];
                mma_bf16(acc[n], Ahi[kt], bh0, bh1);
                mma_bf16(acc[n], Ahi[kt], bl0, bl1);
                mma_bf16(acc[n], Alo[kt], bh0, bh1);
            }
        }

        // ---- partials ----
        {
            float* p = part + w * (16 * 33);
            #pragma unroll
            for (int n = 0; n < 4; ++n) {
                int ci = n * 8 + 2 * tg;
                p[gq * 33 + ci]           = acc[n][0];
                p[gq * 33 + ci + 1]       = acc[n][1];
                p[(gq + 8) * 33 + ci]     = acc[n][2];
                p[(gq + 8) * 33 + ci + 1] = acc[n][3];
            }
        }
        __syncthreads();   // sync1

        // ---- reduce + cell update (tid<64), write packed h ----
        if (tid < 64) {
            float hv[2];
            #pragma unroll
            for (int j2 = 0; j2 < 2; ++j2) {
                int uu = 2 * pr + j2;
                float gs[4];
                #pragma unroll
                for (int q = 0; q < 4; ++q) {
                    int r = uu * 4 + q;
                    float s = xp[j2 * 4 + q];
                    #pragma unroll
                    for (int ww = 0; ww < 8; ++ww)
                        s += part[ww * (16 * 33) + r * 33 + b];
                    gs[q] = s;
                }
                float i_ = sigf(gs[0]);
                float f_ = sigf(gs[1]);
                float g_ = tanh_fast(gs[2]);
                float o_ = sigf(gs[3]);
                float c = f_ * cst[j2] + i_ * g_;
                cst[j2] = c;
                hv[j2] = o_ * tanh_fast(c);
                if (t == T_SEQ - 1) {
                    int u = cta * 4 + uu;
                    out[b * HID + u] = hv[j2];
                    out[BATCH * HID + b * HID + u] = cst[j2];
                }
            }
            unsigned lo;
            unsigned hi = split_pack(hv[0], hv[1], lo);
            int widx = (cta * 2 + pr) * 32 + b;   // k2 = cta*2+pr
            g_hhi[cur ^ 1][widx] = hi;
            g_hlo[cur ^ 1][widx] = lo;
        }

        // ---- sharded-arrival sense-broadcast barrier ----
        __syncthreads();   // sync2: h stores done CTA-wide
        if (tid == 0) {
            red_release(&g_arr[(cta >> 4) * 32]);          // sharded arrival
            const unsigned epoch = (unsigned)(t + 1);
            if (cta == 0) {
                const unsigned need = 128u * epoch;
                for (;;) {
                    unsigned s = 0;
                    #pragma unroll
                    for (int i = 0; i < 8; ++i) s += ld_acquire(&g_arr[i * 32]);
                    if (s >= need) break;
                    __nanosleep(32);
                }
                st_release(&g_go, epoch);                  // broadcast
            } else {
                while (ld_acquire(&g_go) < epoch) { __nanosleep(32); }
            }
        }
        __syncthreads();   // sync3
    }
}

// =====================================================================
// launch
// =====================================================================
extern "C" void kernel_launch(void* const* d_in, const int* in_sizes, int n_in,
                              void* d_out, int out_size)
{
    const float* input = (const float*)d_in[0];
    const float* h0    = (const float*)d_in[1];
    const float* c0    = (const float*)d_in[2];
    const float* W_ih  = (const float*)d_in[3];
    const float* W_hh  = (const float*)d_in[4];
    const float* b_ih  = (const float*)d_in[5];
    const float* b_hh  = (const float*)d_in[6];
    float* out = (float*)d_out;

    cudaFuncSetAttribute(lstm_kernel,
                         cudaFuncAttributeMaxDynamicSharedMemorySize,
                         (int)SMEM_BYTES);
    cudaFuncSetAttribute(xproj_kernel,
                         cudaFuncAttributeMaxDynamicSharedMemorySize,
                         (int)XSMEM_BYTES);

    convert_kernel<<<2048, 256>>>(input, W_ih);
    init_kernel<<<32, 256>>>(h0);
    xproj_kernel<<<dim3(16, 512), 256, XSMEM_BYTES>>>(b_ih, b_hh);
    lstm_kernel<<<NCTA, 256, SMEM_BYTES>>>(W_hh, c0, out);
}

// round 13
// speedup vs baseline: 1.2386x; 1.2386x over previous
#include <cuda_runtime.h>
#include <cuda_bf16.h>
#include <cstdint>

#define T_SEQ 2048
#define BATCH 32
#define DIM   512
#define HID   512
#define G4    2048
#define NJ    (T_SEQ * BATCH)   // 65536
#define NCTA  128               // recurrent CTAs: 4 units each

// ---------------- static device scratch ----------------
__device__ float    g_xproj[(size_t)G4 * NJ];                  // [g][t*32+b] fp32 (512MB)
__device__ unsigned g_xhi[(size_t)BATCH * T_SEQ * DIM / 2];    // bf16 pairs along d
__device__ unsigned g_xlo[(size_t)BATCH * T_SEQ * DIM / 2];
__device__ unsigned g_whi[(size_t)G4 * DIM / 2];
__device__ unsigned g_wlo[(size_t)G4 * DIM / 2];
__device__ unsigned g_hhi[2][(HID / 2) * BATCH];               // word idx = k2*32+b
__device__ unsigned g_hlo[2][(HID / 2) * BATCH];
__device__ unsigned g_arr[8 * 32];   // 8 sharded arrival counters, 128B apart

// ---------------- helpers ----------------
__device__ __forceinline__ void mma_bf16(float c[4], const unsigned a[4],
                                         unsigned b0, unsigned b1) {
    asm volatile(
        "mma.sync.aligned.m16n8k16.row.col.f32.bf16.bf16.f32 "
        "{%0,%1,%2,%3}, {%4,%5,%6,%7}, {%8,%9}, {%0,%1,%2,%3};\n"
        : "+f"(c[0]), "+f"(c[1]), "+f"(c[2]), "+f"(c[3])
        : "r"(a[0]), "r"(a[1]), "r"(a[2]), "r"(a[3]), "r"(b0), "r"(b1));
}

__device__ __forceinline__ unsigned split_pack(float v0, float v1, unsigned& lo_bits) {
    __nv_bfloat162 hi = __floats2bfloat162_rn(v0, v1);
    __nv_bfloat162 lo = __floats2bfloat162_rn(v0 - __bfloat162float(hi.x),
                                              v1 - __bfloat162float(hi.y));
    lo_bits = *reinterpret_cast<unsigned*>(&lo);
    return *reinterpret_cast<unsigned*>(&hi);
}

__device__ __forceinline__ float sigf(float x) {
    return __fdividef(1.f, 1.f + __expf(-x));
}
__device__ __forceinline__ float tanh_fast(float x) {
    return __fdividef(2.f, 1.f + __expf(-2.f * x)) - 1.f;
}

__device__ __forceinline__ void red_release(unsigned* p) {
    asm volatile("red.release.gpu.global.add.u32 [%0], %1;" :: "l"(p), "r"(1u) : "memory");
}
__device__ __forceinline__ unsigned ld_acquire(const unsigned* p) {
    unsigned v;
    asm volatile("ld.acquire.gpu.global.u32 %0, [%1];" : "=r"(v) : "l"(p) : "memory");
    return v;
}

// =====================================================================
// convert: split input & W_ih into bf16 hi/lo packed-pair planes
// =====================================================================
__global__ void convert_kernel(const float* __restrict__ x,
                               const float* __restrict__ wih)
{
    const size_t n_x = (size_t)BATCH * T_SEQ * DIM / 2;
    const size_t n_w = (size_t)G4 * DIM / 2;
    const size_t stride = (size_t)gridDim.x * blockDim.x;
    for (size_t i = blockIdx.x * (size_t)blockDim.x + threadIdx.x;
         i < n_x; i += stride) {
        float2 v = reinterpret_cast<const float2*>(x)[i];
        unsigned lo;
        unsigned hi = split_pack(v.x, v.y, lo);
        g_xhi[i] = hi; g_xlo[i] = lo;
    }
    for (size_t i = blockIdx.x * (size_t)blockDim.x + threadIdx.x;
         i < n_w; i += stride) {
        float2 v = reinterpret_cast<const float2*>(wih)[i];
        unsigned lo;
        unsigned hi = split_pack(v.x, v.y, lo);
        g_whi[i] = hi; g_wlo[i] = lo;
    }
}

// =====================================================================
// init: h planes (buffer 0) from h0, reset arrival counters
// =====================================================================
__global__ void init_kernel(const float* __restrict__ h0)
{
    int i = blockIdx.x * blockDim.x + threadIdx.x;
    if (i < (HID / 2) * BATCH) {
        int k2 = i >> 5, b = i & 31;
        float v0 = h0[b * HID + 2 * k2];
        float v1 = h0[b * HID + 2 * k2 + 1];
        unsigned lo;
        unsigned hi = split_pack(v0, v1, lo);
        g_hhi[0][i] = hi; g_hlo[0][i] = lo;
    }
    if (i < 8 * 32) g_arr[i] = 0u;
}

// =====================================================================
// Phase 1: x_proj via bf16x3 mma, 2-stage pipelined (unchanged from R6)
// =====================================================================
#define SA 20
#define XPLANE (128 * SA)
#define XBUF   (4 * XPLANE)
#define XSMEM_WORDS (2 * XBUF)
#define XSMEM_BYTES (XSMEM_WORDS * 4)

__global__ __launch_bounds__(256) void xproj_kernel(
    const float* __restrict__ b_ih,
    const float* __restrict__ b_hh)
{
    extern __shared__ unsigned xsm[];

    const int tid = threadIdx.x;
    const int w = tid >> 5, lane = tid & 31;
    const int gq = lane >> 2, tg = lane & 3;
    const int gm0 = blockIdx.x * 128;
    const int jn0 = blockIdx.y * 128;
    const int wm = (w >> 2) * 64;
    const int wn = (w & 3) * 32;

    int s_m[2], s_q4[2];
    size_t gwA[2], gwB[2];
    #pragma unroll
    for (int i = 0; i < 2; ++i) {
        int idx = tid + i * 256;
        int m = idx >> 2, q4 = (idx & 3) * 4;
        s_m[i] = m; s_q4[i] = q4;
        gwA[i] = (size_t)(gm0 + m) * (DIM / 2) + q4;
        int b = m & 31;
        int t = (jn0 + m) >> 5;
        gwB[i] = ((size_t)b * T_SEQ + t) * (DIM / 2) + q4;
    }

    float acc[4][4][4];
    #pragma unroll
    for (int m = 0; m < 4; ++m)
        #pragma unroll
        for (int n = 0; n < 4; ++n)
            #pragma unroll
            for (int r = 0; r < 4; ++r) acc[m][n][r] = 0.f;

    uint4 rAh[2], rAl[2], rBh[2], rBl[2];

    #pragma unroll
    for (int i = 0; i < 2; ++i) {
        rAh[i] = *reinterpret_cast<const uint4*>(&g_whi[gwA[i]]);
        rAl[i] = *reinterpret_cast<const uint4*>(&g_wlo[gwA[i]]);
        rBh[i] = *reinterpret_cast<const uint4*>(&g_xhi[gwB[i]]);
        rBl[i] = *reinterpret_cast<const uint4*>(&g_xlo[gwB[i]]);
    }
    {
        unsigned* buf = xsm;
        #pragma unroll
        for (int i = 0; i < 2; ++i) {
            int off = s_m[i] * SA + s_q4[i];
            *reinterpret_cast<uint4*>(&buf[off])              = rAh[i];
            *reinterpret_cast<uint4*>(&buf[XPLANE + off])     = rAl[i];
            *reinterpret_cast<uint4*>(&buf[2 * XPLANE + off]) = rBh[i];
            *reinterpret_cast<uint4*>(&buf[3 * XPLANE + off]) = rBl[i];
        }
    }
    __syncthreads();

    int p = 0;
    for (int c = 0; c < 16; ++c) {
        if (c + 1 < 16) {
            const size_t ko = (size_t)(c + 1) * 16;
            #pragma unroll
            for (int i = 0; i < 2; ++i) {
                rAh[i] = *reinterpret_cast<const uint4*>(&g_whi[gwA[i] + ko]);
                rAl[i] = *reinterpret_cast<const uint4*>(&g_wlo[gwA[i] + ko]);
                rBh[i] = *reinterpret_cast<const uint4*>(&g_xhi[gwB[i] + ko]);
                rBl[i] = *reinterpret_cast<const uint4*>(&g_xlo[gwB[i] + ko]);
            }
        }

        unsigned* Ahs = xsm + p * XBUF;
        unsigned* Als = Ahs + XPLANE;
        unsigned* Bhs = Ahs + 2 * XPLANE;
        unsigned* Bls = Ahs + 3 * XPLANE;

        #pragma unroll
        for (int kt = 0; kt < 2; ++kt) {
            const int k2o = kt * 8;
            unsigned bh[4][2], bl[4][2];
            #pragma unroll
            for (int n = 0; n < 4; ++n) {
                int j = wn + n * 8 + gq;
                bh[n][0] = Bhs[j * SA + k2o + tg];
                bh[n][1] = Bhs[j * SA + k2o + tg + 4];
                bl[n][0] = Bls[j * SA + k2o + tg];
                bl[n][1] = Bls[j * SA + k2o + tg + 4];
            }
            #pragma unroll
            for (int m = 0; m < 4; ++m) {
                int r0 = wm + m * 16 + gq;
                unsigned ah[4], al[4];
                ah[0] = Ahs[r0 * SA + k2o + tg];
                ah[1] = Ahs[(r0 + 8) * SA + k2o + tg];
                ah[2] = Ahs[r0 * SA + k2o + tg + 4];
                ah[3] = Ahs[(r0 + 8) * SA + k2o + tg + 4];
                al[0] = Als[r0 * SA + k2o + tg];
                al[1] = Als[(r0 + 8) * SA + k2o + tg];
                al[2] = Als[r0 * SA + k2o + tg + 4];
                al[3] = Als[(r0 + 8) * SA + k2o + tg + 4];
                #pragma unroll
                for (int n = 0; n < 4; ++n) {
                    mma_bf16(acc[m][n], ah, bh[n][0], bh[n][1]);
                    mma_bf16(acc[m][n], ah, bl[n][0], bl[n][1]);
                    mma_bf16(acc[m][n], al, bh[n][0], bh[n][1]);
                }
            }
        }

        if (c + 1 < 16) {
            unsigned* buf = xsm + (p ^ 1) * XBUF;
            #pragma unroll
            for (int i = 0; i < 2; ++i) {
                int off = s_m[i] * SA + s_q4[i];
                *reinterpret_cast<uint4*>(&buf[off])              = rAh[i];
                *reinterpret_cast<uint4*>(&buf[XPLANE + off])     = rAl[i];
                *reinterpret_cast<uint4*>(&buf[2 * XPLANE + off]) = rBh[i];
                *reinterpret_cast<uint4*>(&buf[3 * XPLANE + off]) = rBl[i];
            }
            __syncthreads();
            p ^= 1;
        }
    }

    #pragma unroll
    for (int m = 0; m < 4; ++m) {
        int g0 = gm0 + wm + m * 16 + gq;
        float bi0 = __ldg(b_ih + g0) + __ldg(b_hh + g0);
        float bi1 = __ldg(b_ih + g0 + 8) + __ldg(b_hh + g0 + 8);
        #pragma unroll
        for (int n = 0; n < 4; ++n) {
            int j0 = jn0 + wn + n * 8 + tg * 2;
            float2 v0 = make_float2(acc[m][n][0] + bi0, acc[m][n][1] + bi0);
            float2 v1 = make_float2(acc[m][n][2] + bi1, acc[m][n][3] + bi1);
            *reinterpret_cast<float2*>(g_xproj + (size_t)g0 * NJ + j0) = v0;
            *reinterpret_cast<float2*>(g_xproj + (size_t)(g0 + 8) * NJ + j0) = v1;
        }
    }
}

// =====================================================================
// Phase 2: persistent recurrent kernel (R6 design) with:
//   - sharded arrivals (8 lines), every CTA self-sums in a tight poll
//   - 128-thread cell phase (1 unit/thread), bf16 halfword h stores
// =====================================================================
#define HSW 40
#define SMEM_WORDS (2 * 256 * HSW + 8 * 16 * 33)
#define SMEM_BYTES (SMEM_WORDS * 4)

__global__ __launch_bounds__(256) void lstm_kernel(
    const float* __restrict__ W_hh,
    const float* __restrict__ c0,
    float* __restrict__ out)
{
    extern __shared__ unsigned smw[];
    unsigned* s_hhi = smw;                    // [256 k2][HSW]
    unsigned* s_hlo = smw + 256 * HSW;
    float*    part  = reinterpret_cast<float*>(smw + 2 * 256 * HSW); // [8][16][33]

    const int tid = threadIdx.x;
    const int cta = blockIdx.x;
    const int w = tid >> 5, lane = tid & 31;
    const int gq = lane >> 2, tg = lane & 3;

    // ---- W_hh frags into registers (hi/lo), once ----
    unsigned Ahi[4][4], Alo[4][4];
    #pragma unroll
    for (int kt = 0; kt < 4; ++kt) {
        #pragma unroll
        for (int i = 0; i < 4; ++i) {
            int r   = gq + ((i & 1) << 3);
            int k2l = tg + ((i >> 1) << 2);
            int kg  = w * 64 + kt * 16 + k2l * 2;
            int G   = (r & 3) * HID + cta * 4 + (r >> 2);
            float w0 = __ldg(W_hh + (size_t)G * HID + kg);
            float w1 = __ldg(W_hh + (size_t)G * HID + kg + 1);
            unsigned lo;
            Ahi[kt][i] = split_pack(w0, w1, lo);
            Alo[kt][i] = lo;
        }
    }

    // cell threads: tid<128, warp w = unit index (0..3), batch = lane
    const int unit = cta * 4 + w;             // valid for tid<128
    float cst = 0.f;
    if (tid < 128) cst = __ldg(c0 + lane * HID + unit);

    for (int t = 0; t < T_SEQ; ++t) {
        const int cur = t & 1;

        // ---- xp(t) loads fired early; consumed after sync1 ----
        float xp[4];
        if (tid < 128) {
            #pragma unroll
            for (int q = 0; q < 4; ++q) {
                int G = q * HID + unit;
                xp[q] = __ldg(&g_xproj[(size_t)G * NJ + (size_t)t * 32 + lane]);
            }
        }

        // ---- per-warp self-staging: warp w stages its own 32 k2 rows ----
        #pragma unroll
        for (int i = 0; i < 8; ++i) {
            int lin = w * 256 + i * 32 + lane;     // uint4 idx within plane
            int k2 = lin >> 3, b4 = (lin & 7) * 4;
            uint4 vh = __ldcg(reinterpret_cast<const uint4*>(&g_hhi[cur][lin * 4]));
            uint4 vl = __ldcg(reinterpret_cast<const uint4*>(&g_hlo[cur][lin * 4]));
            *reinterpret_cast<uint4*>(&s_hhi[k2 * HSW + b4]) = vh;
            *reinterpret_cast<uint4*>(&s_hlo[k2 * HSW + b4]) = vl;
        }
        // no syncthreads: warp consumes only its own staged slice

        // ---- mma: warp w covers k2 in [w*32, w*32+32) ----
        float acc[4][4];
        #pragma unroll
        for (int n = 0; n < 4; ++n)
            #pragma unroll
            for (int r = 0; r < 4; ++r) acc[n][r] = 0.f;

        #pragma unroll
        for (int kt = 0; kt < 4; ++kt) {
            const int base = w * 32 + kt * 8;
            #pragma unroll
            for (int n = 0; n < 4; ++n) {
                int col = n * 8 + gq;
                unsigned bh0 = s_hhi[(base + tg) * HSW + col];
                unsigned bh1 = s_hhi[(base + tg + 4) * HSW + col];
                unsigned bl0 = s_hlo[(base + tg) * HSW + col];
                unsigned bl1 = s_hlo[(base + tg + 4) * HSW + col];
                mma_bf16(acc[n], Ahi[kt], bh0, bh1);
                mma_bf16(acc[n], Ahi[kt], bl0, bl1);
                mma_bf16(acc[n], Alo[kt], bh0, bh1);
            }
        }

        // ---- partials ----
        {
            float* p = part + w * (16 * 33);
            #pragma unroll
            for (int n = 0; n < 4; ++n) {
                int ci = n * 8 + 2 * tg;
                p[gq * 33 + ci]           = acc[n][0];
                p[gq * 33 + ci + 1]       = acc[n][1];
                p[(gq + 8) * 33 + ci]     = acc[n][2];
                p[(gq + 8) * 33 + ci + 1] = acc[n][3];
            }
        }
        __syncthreads();   // sync1

        // ---- reduce + cell update (tid<128, 1 unit/thread), halfword h ----
        if (tid < 128) {
            float gs[4];
            #pragma unroll
            for (int q = 0; q < 4; ++q) {
                int r = w * 4 + q;
                float s = xp[q];
                #pragma unroll
                for (int ww = 0; ww < 8; ++ww)
                    s += part[ww * (16 * 33) + r * 33 + lane];
                gs[q] = s;
            }
            float i_ = sigf(gs[0]);
            float f_ = sigf(gs[1]);
            float g_ = tanh_fast(gs[2]);
            float o_ = sigf(gs[3]);
            float c = f_ * cst + i_ * g_;
            cst = c;
            float hv = o_ * tanh_fast(c);
            if (t == T_SEQ - 1) {
                out[lane * HID + unit] = hv;
                out[BATCH * HID + lane * HID + unit] = c;
            }
            __nv_bfloat16 hb = __float2bfloat16(hv);
            __nv_bfloat16 lb = __float2bfloat16(hv - __bfloat162float(hb));
            int hw = ((unit >> 1) * 32 + lane) * 2 + (unit & 1);
            reinterpret_cast<__nv_bfloat16*>(g_hhi[cur ^ 1])[hw] = hb;
            reinterpret_cast<__nv_bfloat16*>(g_hlo[cur ^ 1])[hw] = lb;
        }

        // ---- barrier: sharded arrivals, self-summing tight poll ----
        __syncthreads();   // sync2: h stores done CTA-wide
        if (tid == 0) {
            red_release(&g_arr[(cta >> 4) * 32]);
            const unsigned need = 128u * (unsigned)(t + 1);
            for (;;) {
                unsigned s = 0;
                #pragma unroll
                for (int i = 0; i < 8; ++i) s += ld_acquire(&g_arr[i * 32]);
                if (s >= need) break;
            }
        }
        __syncthreads();   // sync3
    }
}

// =====================================================================
// launch
// =====================================================================
extern "C" void kernel_launch(void* const* d_in, const int* in_sizes, int n_in,
                              void* d_out, int out_size)
{
    const float* input = (const float*)d_in[0];
    const float* h0    = (const float*)d_in[1];
    const float* c0    = (const float*)d_in[2];
    const float* W_ih  = (const float*)d_in[3];
    const float* W_hh  = (const float*)d_in[4];
    const float* b_ih  = (const float*)d_in[5];
    const float* b_hh  = (const float*)d_in[6];
    float* out = (float*)d_out;

    cudaFuncSetAttribute(lstm_kernel,
                         cudaFuncAttributeMaxDynamicSharedMemorySize,
                         (int)SMEM_BYTES);
    cudaFuncSetAttribute(xproj_kernel,
                         cudaFuncAttributeMaxDynamicSharedMemorySize,
                         (int)XSMEM_BYTES);

    convert_kernel<<<2048, 256>>>(input, W_ih);
    init_kernel<<<32, 256>>>(h0);
    xproj_kernel<<<dim3(16, 512), 256, XSMEM_BYTES>>>(b_ih, b_hh);
    lstm_kernel<<<NCTA, 256, SMEM_BYTES>>>(W_hh, c0, out);
}

// round 15
// speedup vs baseline: 2.1257x; 1.7162x over previous
#include <cuda_runtime.h>
#include <cuda_bf16.h>
#include <cstdint>

#define T_SEQ 2048
#define BATCH 32
#define DIM   512
#define HID   512
#define G4    2048
#define NJ    (T_SEQ * BATCH)   // 65536
#define NCTA  128               // recurrent CTAs: 4 units each

// ---------------- static device scratch ----------------
__device__ float    g_xproj[(size_t)G4 * NJ];                  // [g][t*32+b] fp32 (512MB)
__device__ unsigned g_xhi[(size_t)BATCH * T_SEQ * DIM / 2];    // bf16 pairs along d
__device__ unsigned g_xlo[(size_t)BATCH * T_SEQ * DIM / 2];
__device__ unsigned g_whi[(size_t)G4 * DIM / 2];
__device__ unsigned g_wlo[(size_t)G4 * DIM / 2];
__device__ unsigned g_hhi[2][(HID / 2) * BATCH];               // word idx = k2*32+b
__device__ unsigned g_hlo[2][(HID / 2) * BATCH];
__device__ unsigned g_bar;

// ---------------- helpers ----------------
__device__ __forceinline__ void mma_bf16(float c[4], const unsigned a[4],
                                         unsigned b0, unsigned b1) {
    asm volatile(
        "mma.sync.aligned.m16n8k16.row.col.f32.bf16.bf16.f32 "
        "{%0,%1,%2,%3}, {%4,%5,%6,%7}, {%8,%9}, {%0,%1,%2,%3};\n"
        : "+f"(c[0]), "+f"(c[1]), "+f"(c[2]), "+f"(c[3])
        : "r"(a[0]), "r"(a[1]), "r"(a[2]), "r"(a[3]), "r"(b0), "r"(b1));
}

__device__ __forceinline__ unsigned split_pack(float v0, float v1, unsigned& lo_bits) {
    __nv_bfloat162 hi = __floats2bfloat162_rn(v0, v1);
    __nv_bfloat162 lo = __floats2bfloat162_rn(v0 - __bfloat162float(hi.x),
                                              v1 - __bfloat162float(hi.y));
    lo_bits = *reinterpret_cast<unsigned*>(&lo);
    return *reinterpret_cast<unsigned*>(&hi);
}

__device__ __forceinline__ float sigf(float x) {
    return __fdividef(1.f, 1.f + __expf(-x));
}
__device__ __forceinline__ float tanh_fast(float x) {
    return __fdividef(2.f, 1.f + __expf(-2.f * x)) - 1.f;
}

__device__ __forceinline__ void bar_arrive_release() {
    unsigned* p = &g_bar;
    asm volatile("red.release.gpu.global.add.u32 [%0], %1;" :: "l"(p), "r"(1u) : "memory");
}
__device__ __forceinline__ unsigned bar_load_acquire() {
    unsigned v;
    unsigned* p = &g_bar;
    asm volatile("ld.acquire.gpu.global.u32 %0, [%1];" : "=r"(v) : "l"(p) : "memory");
    return v;
}

// =====================================================================
// convert: split input & W_ih into bf16 hi/lo packed-pair planes
// =====================================================================
__global__ void convert_kernel(const float* __restrict__ x,
                               const float* __restrict__ wih)
{
    const size_t n_x = (size_t)BATCH * T_SEQ * DIM / 2;
    const size_t n_w = (size_t)G4 * DIM / 2;
    const size_t stride = (size_t)gridDim.x * blockDim.x;
    for (size_t i = blockIdx.x * (size_t)blockDim.x + threadIdx.x;
         i < n_x; i += stride) {
        float2 v = reinterpret_cast<const float2*>(x)[i];
        unsigned lo;
        unsigned hi = split_pack(v.x, v.y, lo);
        g_xhi[i] = hi; g_xlo[i] = lo;
    }
    for (size_t i = blockIdx.x * (size_t)blockDim.x + threadIdx.x;
         i < n_w; i += stride) {
        float2 v = reinterpret_cast<const float2*>(wih)[i];
        unsigned lo;
        unsigned hi = split_pack(v.x, v.y, lo);
        g_whi[i] = hi; g_wlo[i] = lo;
    }
}

// =====================================================================
// init: h planes (buffer 0) from h0, reset barrier
// =====================================================================
__global__ void init_kernel(const float* __restrict__ h0)
{
    int i = blockIdx.x * blockDim.x + threadIdx.x;
    if (i < (HID / 2) * BATCH) {
        int k2 = i >> 5, b = i & 31;
        float v0 = h0[b * HID + 2 * k2];
        float v1 = h0[b * HID + 2 * k2 + 1];
        unsigned lo;
        unsigned hi = split_pack(v0, v1, lo);
        g_hhi[0][i] = hi; g_hlo[0][i] = lo;
    }
    if (i == 0) g_bar = 0u;
}

// =====================================================================
// Phase 1: x_proj via bf16x3 mma, 2-stage pipelined.
//   GRID SWAPPED vs R6: blockIdx.x = g-block (16, fastest), blockIdx.y =
//   j-block (512). Consecutive CTAs share one x-tile (L2 reuse); W planes
//   stay L2-resident. DRAM reads of x-planes drop ~16x.
// =====================================================================
#define SA 20
#define XPLANE (128 * SA)
#define XBUF   (4 * XPLANE)
#define XSMEM_WORDS (2 * XBUF)
#define XSMEM_BYTES (XSMEM_WORDS * 4)

__global__ __launch_bounds__(256) void xproj_kernel(
    const float* __restrict__ b_ih,
    const float* __restrict__ b_hh)
{
    extern __shared__ unsigned xsm[];

    const int tid = threadIdx.x;
    const int w = tid >> 5, lane = tid & 31;
    const int gq = lane >> 2, tg = lane & 3;
    const int gm0 = blockIdx.x * 128;   // g-block (16)  -- swapped
    const int jn0 = blockIdx.y * 128;   // j-block (512) -- swapped
    const int wm = (w >> 2) * 64;
    const int wn = (w & 3) * 32;

    int s_m[2], s_q4[2];
    size_t gwA[2], gwB[2];
    #pragma unroll
    for (int i = 0; i < 2; ++i) {
        int idx = tid + i * 256;
        int m = idx >> 2, q4 = (idx & 3) * 4;
        s_m[i] = m; s_q4[i] = q4;
        gwA[i] = (size_t)(gm0 + m) * (DIM / 2) + q4;
        int b = m & 31;
        int t = (jn0 + m) >> 5;
        gwB[i] = ((size_t)b * T_SEQ + t) * (DIM / 2) + q4;
    }

    float acc[4][4][4];
    #pragma unroll
    for (int m = 0; m < 4; ++m)
        #pragma unroll
        for (int n = 0; n < 4; ++n)
            #pragma unroll
            for (int r = 0; r < 4; ++r) acc[m][n][r] = 0.f;

    uint4 rAh[2], rAl[2], rBh[2], rBl[2];

    #pragma unroll
    for (int i = 0; i < 2; ++i) {
        rAh[i] = *reinterpret_cast<const uint4*>(&g_whi[gwA[i]]);
        rAl[i] = *reinterpret_cast<const uint4*>(&g_wlo[gwA[i]]);
        rBh[i] = *reinterpret_cast<const uint4*>(&g_xhi[gwB[i]]);
        rBl[i] = *reinterpret_cast<const uint4*>(&g_xlo[gwB[i]]);
    }
    {
        unsigned* buf = xsm;
        #pragma unroll
        for (int i = 0; i < 2; ++i) {
            int off = s_m[i] * SA + s_q4[i];
            *reinterpret_cast<uint4*>(&buf[off])              = rAh[i];
            *reinterpret_cast<uint4*>(&buf[XPLANE + off])     = rAl[i];
            *reinterpret_cast<uint4*>(&buf[2 * XPLANE + off]) = rBh[i];
            *reinterpret_cast<uint4*>(&buf[3 * XPLANE + off]) = rBl[i];
        }
    }
    __syncthreads();

    int p = 0;
    for (int c = 0; c < 16; ++c) {
        if (c + 1 < 16) {
            const size_t ko = (size_t)(c + 1) * 16;
            #pragma unroll
            for (int i = 0; i < 2; ++i) {
                rAh[i] = *reinterpret_cast<const uint4*>(&g_whi[gwA[i] + ko]);
                rAl[i] = *reinterpret_cast<const uint4*>(&g_wlo[gwA[i] + ko]);
                rBh[i] = *reinterpret_cast<const uint4*>(&g_xhi[gwB[i] + ko]);
                rBl[i] = *reinterpret_cast<const uint4*>(&g_xlo[gwB[i] + ko]);
            }
        }

        unsigned* Ahs = xsm + p * XBUF;
        unsigned* Als = Ahs + XPLANE;
        unsigned* Bhs = Ahs + 2 * XPLANE;
        unsigned* Bls = Ahs + 3 * XPLANE;

        #pragma unroll
        for (int kt = 0; kt < 2; ++kt) {
            const int k2o = kt * 8;
            unsigned bh[4][2], bl[4][2];
            #pragma unroll
            for (int n = 0; n < 4; ++n) {
                int j = wn + n * 8 + gq;
                bh[n][0] = Bhs[j * SA + k2o + tg];
                bh[n][1] = Bhs[j * SA + k2o + tg + 4];
                bl[n][0] = Bls[j * SA + k2o + tg];
                bl[n][1] = Bls[j * SA + k2o + tg + 4];
            }
            #pragma unroll
            for (int m = 0; m < 4; ++m) {
                int r0 = wm + m * 16 + gq;
                unsigned ah[4], al[4];
                ah[0] = Ahs[r0 * SA + k2o + tg];
                ah[1] = Ahs[(r0 + 8) * SA + k2o + tg];
                ah[2] = Ahs[r0 * SA + k2o + tg + 4];
                ah[3] = Ahs[(r0 + 8) * SA + k2o + tg + 4];
                al[0] = Als[r0 * SA + k2o + tg];
                al[1] = Als[(r0 + 8) * SA + k2o + tg];
                al[2] = Als[r0 * SA + k2o + tg + 4];
                al[3] = Als[(r0 + 8) * SA + k2o + tg + 4];
                #pragma unroll
                for (int n = 0; n < 4; ++n) {
                    mma_bf16(acc[m][n], ah, bh[n][0], bh[n][1]);
                    mma_bf16(acc[m][n], ah, bl[n][0], bl[n][1]);
                    mma_bf16(acc[m][n], al, bh[n][0], bh[n][1]);
                }
            }
        }

        if (c + 1 < 16) {
            unsigned* buf = xsm + (p ^ 1) * XBUF;
            #pragma unroll
            for (int i = 0; i < 2; ++i) {
                int off = s_m[i] * SA + s_q4[i];
                *reinterpret_cast<uint4*>(&buf[off])              = rAh[i];
                *reinterpret_cast<uint4*>(&buf[XPLANE + off])     = rAl[i];
                *reinterpret_cast<uint4*>(&buf[2 * XPLANE + off]) = rBh[i];
                *reinterpret_cast<uint4*>(&buf[3 * XPLANE + off]) = rBl[i];
            }
            __syncthreads();
            p ^= 1;
        }
    }

    #pragma unroll
    for (int m = 0; m < 4; ++m) {
        int g0 = gm0 + wm + m * 16 + gq;
        float bi0 = __ldg(b_ih + g0) + __ldg(b_hh + g0);
        float bi1 = __ldg(b_ih + g0 + 8) + __ldg(b_hh + g0 + 8);
        #pragma unroll
        for (int n = 0; n < 4; ++n) {
            int j0 = jn0 + wn + n * 8 + tg * 2;
            float2 v0 = make_float2(acc[m][n][0] + bi0, acc[m][n][1] + bi0);
            float2 v1 = make_float2(acc[m][n][2] + bi1, acc[m][n][3] + bi1);
            *reinterpret_cast<float2*>(g_xproj + (size_t)g0 * NJ + j0) = v0;
            *reinterpret_cast<float2*>(g_xproj + (size_t)(g0 + 8) * NJ + j0) = v1;
        }
    }
}

// =====================================================================
// Phase 2: persistent recurrent kernel — BYTE-IDENTICAL to R6 (7691.7us).
// =====================================================================
#define HSW 40
#define SMEM_WORDS (2 * 256 * HSW + 8 * 16 * 33)
#define SMEM_BYTES (SMEM_WORDS * 4)

__global__ __launch_bounds__(256) void lstm_kernel(
    const float* __restrict__ W_hh,
    const float* __restrict__ c0,
    float* __restrict__ out)
{
    extern __shared__ unsigned smw[];
    unsigned* s_hhi = smw;                    // [256 k2][HSW]
    unsigned* s_hlo = smw + 256 * HSW;
    float*    part  = reinterpret_cast<float*>(smw + 2 * 256 * HSW); // [8][16][33]

    const int tid = threadIdx.x;
    const int cta = blockIdx.x;
    const int w = tid >> 5, lane = tid & 31;
    const int gq = lane >> 2, tg = lane & 3;

    // ---- W_hh frags into registers (hi/lo), once ----
    unsigned Ahi[4][4], Alo[4][4];
    #pragma unroll
    for (int kt = 0; kt < 4; ++kt) {
        #pragma unroll
        for (int i = 0; i < 4; ++i) {
            int r   = gq + ((i & 1) << 3);
            int k2l = tg + ((i >> 1) << 2);
            int kg  = w * 64 + kt * 16 + k2l * 2;
            int G   = (r & 3) * HID + cta * 4 + (r >> 2);
            float w0 = __ldg(W_hh + (size_t)G * HID + kg);
            float w1 = __ldg(W_hh + (size_t)G * HID + kg + 1);
            unsigned lo;
            Ahi[kt][i] = split_pack(w0, w1, lo);
            Alo[kt][i] = lo;
        }
    }

    // cell threads: tid<64, pair pr = tid>>5 (units 2pr,2pr+1), batch b
    const int pr = tid >> 5;
    const int b  = lane;
    float cst[2] = {0.f, 0.f};
    if (tid < 64) {
        cst[0] = __ldg(c0 + b * HID + cta * 4 + 2 * pr);
        cst[1] = __ldg(c0 + b * HID + cta * 4 + 2 * pr + 1);
    }

    unsigned target = NCTA;

    for (int t = 0; t < T_SEQ; ++t) {
        const int cur = t & 1;

        // ---- xp prefetch (cell threads) ----
        float xp[8];
        if (tid < 64) {
            #pragma unroll
            for (int j2 = 0; j2 < 2; ++j2)
                #pragma unroll
                for (int q = 0; q < 4; ++q) {
                    int G = q * HID + cta * 4 + 2 * pr + j2;
                    xp[j2 * 4 + q] =
                        __ldg(&g_xproj[(size_t)G * NJ + (size_t)t * 32 + b]);
                }
        }

        // ---- per-warp self-staging: warp w stages its own 32 k2 rows ----
        #pragma unroll
        for (int i = 0; i < 8; ++i) {
            int lin = w * 256 + i * 32 + lane;     // uint4 idx within plane
            int k2 = lin >> 3, b4 = (lin & 7) * 4;
            uint4 vh = __ldcg(reinterpret_cast<const uint4*>(&g_hhi[cur][lin * 4]));
            uint4 vl = __ldcg(reinterpret_cast<const uint4*>(&g_hlo[cur][lin * 4]));
            *reinterpret_cast<uint4*>(&s_hhi[k2 * HSW + b4]) = vh;
            *reinterpret_cast<uint4*>(&s_hlo[k2 * HSW + b4]) = vl;
        }
        // no syncthreads: warp consumes only its own staged slice

        // ---- mma: warp w covers k2 in [w*32, w*32+32) ----
        float acc[4][4];
        #pragma unroll
        for (int n = 0; n < 4; ++n)
            #pragma unroll
            for (int r = 0; r < 4; ++r) acc[n][r] = 0.f;

        #pragma unroll
        for (int kt = 0; kt < 4; ++kt) {
            const int base = w * 32 + kt * 8;
            #pragma unroll
            for (int n = 0; n < 4; ++n) {
                int col = n * 8 + gq;
                unsigned bh0 = s_hhi[(base + tg) * HSW + col];
                unsigned bh1 = s_hhi[(base + tg + 4) * HSW + col];
                unsigned bl0 = s_hlo[(base + tg) * HSW + col];
                unsigned bl1 = s_hlo[(base + tg + 4) * HSW + col];
                mma_bf16(acc[n], Ahi[kt], bh0, bh1);
                mma_bf16(acc[n], Ahi[kt], bl0, bl1);
                mma_bf16(acc[n], Alo[kt], bh0, bh1);
            }
        }

        // ---- partials ----
        {
            float* p = part + w * (16 * 33);
            #pragma unroll
            for (int n = 0; n < 4; ++n) {
                int ci = n * 8 + 2 * tg;
                p[gq * 33 + ci]           = acc[n][0];
                p[gq * 33 + ci + 1]       = acc[n][1];
                p[(gq + 8) * 33 + ci]     = acc[n][2];
                p[(gq + 8) * 33 + ci + 1] = acc[n][3];
            }
        }
        __syncthreads();   // sync1

        // ---- reduce + cell update (tid<64), write packed h ----
        if (tid < 64) {
            float hv[2];
            #pragma unroll
            for (int j2 = 0; j2 < 2; ++j2) {
                int uu = 2 * pr + j2;
                float gs[4];
                #pragma unroll
                for (int q = 0; q < 4; ++q) {
                    int r = uu * 4 + q;
                    float s = xp[j2 * 4 + q];
                    #pragma unroll
                    for (int ww = 0; ww < 8; ++ww)
                        s += part[ww * (16 * 33) + r * 33 + b];
                    gs[q] = s;
                }
                float i_ = sigf(gs[0]);
                float f_ = sigf(gs[1]);
                float g_ = tanh_fast(gs[2]);
                float o_ = sigf(gs[3]);
                float c = f_ * cst[j2] + i_ * g_;
                cst[j2] = c;
                hv[j2] = o_ * tanh_fast(c);
                if (t == T_SEQ - 1) {
                    int u = cta * 4 + uu;
                    out[b * HID + u] = hv[j2];
                    out[BATCH * HID + b * HID + u] = cst[j2];
                }
            }
            unsigned lo;
            unsigned hi = split_pack(hv[0], hv[1], lo);
            int widx = (cta * 2 + pr) * 32 + b;   // k2 = cta*2+pr
            g_hhi[cur ^ 1][widx] = hi;
            g_hlo[cur ^ 1][widx] = lo;
        }

        // ---- grid barrier: release arrive, acquire poll ----
        __syncthreads();   // sync2
        if (tid == 0) {
            bar_arrive_release();
            while (bar_load_acquire() < target) { }
        }
        __syncthreads();   // sync3
        target += NCTA;
    }
}

// =====================================================================
// launch
// =====================================================================
extern "C" void kernel_launch(void* const* d_in, const int* in_sizes, int n_in,
                              void* d_out, int out_size)
{
    const float* input = (const float*)d_in[0];
    const float* h0    = (const float*)d_in[1];
    const float* c0    = (const float*)d_in[2];
    const float* W_ih  = (const float*)d_in[3];
    const float* W_hh  = (const float*)d_in[4];
    const float* b_ih  = (const float*)d_in[5];
    const float* b_hh  = (const float*)d_in[6];
    float* out = (float*)d_out;

    cudaFuncSetAttribute(lstm_kernel,
                         cudaFuncAttributeMaxDynamicSharedMemorySize,
                         (int)SMEM_BYTES);
    cudaFuncSetAttribute(xproj_kernel,
                         cudaFuncAttributeMaxDynamicSharedMemorySize,
                         (int)XSMEM_BYTES);

    convert_kernel<<<2048, 256>>>(input, W_ih);
    init_kernel<<<32, 256>>>(h0);
    xproj_kernel<<<dim3(16, 512), 256, XSMEM_BYTES>>>(b_ih, b_hh);
    lstm_kernel<<<NCTA, 256, SMEM_BYTES>>>(W_hh, c0, out);
}